// round 3
// baseline (speedup 1.0000x reference)
#include <cuda_runtime.h>
#include <math.h>

#define NROWS 384
#define SLEN  1024
#define CIN   256
#define CH    32
#define NH    8
#define HC    256   // NH*CH

// Scratch (no cudaMalloc allowed): ~101 MB of __device__ globals.
__device__ float g_q_buf[NROWS * HC];
__device__ float g_o_buf[NROWS * HC];
__device__ float g_k_buf[(size_t)NROWS * SLEN * CH];
__device__ float g_v_buf[(size_t)NROWS * SLEN * CH];

// ---------------------------------------------------------------------------
// Kernel 1: masked mean over S, then q = (mean @ Wq) * C^-0.5
// grid = 384 rows, block = 256 (thread t = channel / output column)
// ---------------------------------------------------------------------------
__global__ void q_kernel(const float* __restrict__ m,
                         const float* __restrict__ mask,
                         const float* __restrict__ Wq) {
    int n = blockIdx.x, t = threadIdx.x;
    const float* mrow = m + (size_t)n * SLEN * CIN;
    const float* mk   = mask + (size_t)n * SLEN;

    float qs = 0.f;
    #pragma unroll 4
    for (int s = 0; s < SLEN; s++) {
        qs = fmaf(mrow[(size_t)s * CIN + t], mk[s], qs);
    }
    float ms = 0.f;
    for (int s = t; s < SLEN; s += 256) ms += mk[s];

    __shared__ float red[256];
    red[t] = ms;
    __syncthreads();
    for (int off = 128; off > 0; off >>= 1) {
        if (t < off) red[t] += red[t + off];
        __syncthreads();
    }
    float denom = red[0] + 1e-10f;

    __shared__ float qm[CIN];
    qm[t] = qs / denom;
    __syncthreads();

    float acc = 0.f;
    #pragma unroll 8
    for (int c = 0; c < CIN; c++) acc = fmaf(qm[c], Wq[c * HC + t], acc);
    g_q_buf[n * HC + t] = acc * 0.17677669529663687f;  // 32^-0.5
}

// ---------------------------------------------------------------------------
// Kernel 2: k = m@Wk, v = m@Wv as one [393216,256]@[256,64] SGEMM
// BM=128, BN=64, BK=16, 128 threads, 8x8 register tile per thread
// ---------------------------------------------------------------------------
__global__ void kv_kernel(const float* __restrict__ m,
                          const float* __restrict__ Wk,
                          const float* __restrict__ Wv) {
    __shared__ float As[16][128];
    __shared__ float Bs[16][64];
    int t  = threadIdx.x;
    int tm = t >> 3;   // 0..15
    int tn = t & 7;    // 0..7
    long r0 = (long)blockIdx.x * 128;

    float acc[8][8];
    #pragma unroll
    for (int i = 0; i < 8; i++)
        #pragma unroll
        for (int j = 0; j < 8; j++) acc[i][j] = 0.f;

    for (int kk = 0; kk < CIN; kk += 16) {
        // load A tile (transposed into smem): 512 float4s, 4 per thread
        #pragma unroll
        for (int q = 0; q < 4; q++) {
            int f   = t + q * 128;
            int row = f >> 2;
            int cq  = (f & 3) << 2;
            float4 v4 = *reinterpret_cast<const float4*>(
                m + (r0 + row) * (long)CIN + kk + cq);
            As[cq + 0][row] = v4.x;
            As[cq + 1][row] = v4.y;
            As[cq + 2][row] = v4.z;
            As[cq + 3][row] = v4.w;
        }
        // load B tile (Wk || Wv): 256 float4s, 2 per thread
        #pragma unroll
        for (int q = 0; q < 2; q++) {
            int f  = t + q * 128;
            int k  = f >> 4;
            int j4 = f & 15;
            float4 v4;
            if (j4 < 8)
                v4 = *reinterpret_cast<const float4*>(Wk + (kk + k) * CH + j4 * 4);
            else
                v4 = *reinterpret_cast<const float4*>(Wv + (kk + k) * CH + (j4 - 8) * 4);
            *reinterpret_cast<float4*>(&Bs[k][j4 * 4]) = v4;
        }
        __syncthreads();

        #pragma unroll
        for (int k = 0; k < 16; k++) {
            float a[8], b[8];
            *reinterpret_cast<float4*>(a)     = *reinterpret_cast<const float4*>(&As[k][tm * 8]);
            *reinterpret_cast<float4*>(a + 4) = *reinterpret_cast<const float4*>(&As[k][tm * 8 + 4]);
            *reinterpret_cast<float4*>(b)     = *reinterpret_cast<const float4*>(&Bs[k][tn * 8]);
            *reinterpret_cast<float4*>(b + 4) = *reinterpret_cast<const float4*>(&Bs[k][tn * 8 + 4]);
            #pragma unroll
            for (int i = 0; i < 8; i++)
                #pragma unroll
                for (int j = 0; j < 8; j++)
                    acc[i][j] = fmaf(a[i], b[j], acc[i][j]);
        }
        __syncthreads();
    }

    #pragma unroll
    for (int i = 0; i < 8; i++) {
        long r = r0 + tm * 8 + i;
        #pragma unroll
        for (int j = 0; j < 8; j += 4) {
            int col = tn * 8 + j;
            float4 v4 = make_float4(acc[i][j], acc[i][j + 1], acc[i][j + 2], acc[i][j + 3]);
            if (col < CH)
                *reinterpret_cast<float4*>(g_k_buf + r * CH + col) = v4;
            else
                *reinterpret_cast<float4*>(g_v_buf + r * CH + (col - CH)) = v4;
        }
    }
}

// ---------------------------------------------------------------------------
// Kernel 3: logits a[h,s] = q[h]·k[s] + INF*(mask-1), per-head softmax over S,
// o[h,c] = sum_s p[h,s] v[s,c].  grid = 384, block = 256 (8 warps = 8 heads).
// ---------------------------------------------------------------------------
__global__ void attn_kernel(const float* __restrict__ mask) {
    int n = blockIdx.x, t = threadIdx.x;
    __shared__ float q_sm[HC];
    __shared__ float p_sm[NH * SLEN];  // 32 KB

    q_sm[t] = g_q_buf[n * HC + t];
    __syncthreads();

    const float* krow = g_k_buf + (size_t)n * SLEN * CH;
    const float* vrow = g_v_buf + (size_t)n * SLEN * CH;
    const float* mk   = mask + (size_t)n * SLEN;

    for (int s = t; s < SLEN; s += 256) {
        float kreg[32];
        #pragma unroll
        for (int q = 0; q < 8; q++)
            *reinterpret_cast<float4*>(kreg + q * 4) =
                *reinterpret_cast<const float4*>(krow + (size_t)s * CH + q * 4);
        float bias = 1e9f * (mk[s] - 1.0f);
        #pragma unroll
        for (int h = 0; h < NH; h++) {
            float d = 0.f;
            #pragma unroll
            for (int j = 0; j < 32; j++) d = fmaf(q_sm[h * 32 + j], kreg[j], d);
            p_sm[h * SLEN + s] = d + bias;
        }
    }
    __syncthreads();

    int w = t >> 5, lane = t & 31;
    float mx = -3.0e38f;
    for (int s = lane; s < SLEN; s += 32) mx = fmaxf(mx, p_sm[w * SLEN + s]);
    #pragma unroll
    for (int off = 16; off > 0; off >>= 1)
        mx = fmaxf(mx, __shfl_xor_sync(0xffffffffu, mx, off));

    float sum = 0.f;
    for (int s = lane; s < SLEN; s += 32) {
        float e = __expf(p_sm[w * SLEN + s] - mx);
        p_sm[w * SLEN + s] = e;
        sum += e;
    }
    #pragma unroll
    for (int off = 16; off > 0; off >>= 1)
        sum += __shfl_xor_sync(0xffffffffu, sum, off);
    float inv = 1.f / sum;
    for (int s = lane; s < SLEN; s += 32) p_sm[w * SLEN + s] *= inv;
    __syncthreads();

    int h = t >> 5, ch = t & 31;
    float acc = 0.f;
    #pragma unroll 4
    for (int s = 0; s < SLEN; s++)
        acc = fmaf(p_sm[h * SLEN + s], vrow[(size_t)s * CH + ch], acc);
    g_o_buf[n * HC + t] = acc;
}

// ---------------------------------------------------------------------------
// Kernel 4 (dominant): per CTA, 64 tokens of one row.
//   G = sigmoid(M@Wg + bg) * o_bcast   (staged fp32 in smem, 64KB)
//   out = G@Wo + bo
// 256 threads, 8x8 register tile, BM=64, BN=256, BK=16.  84 KB dynamic smem.
// ---------------------------------------------------------------------------
__global__ void out_kernel(const float* __restrict__ m,
                           const float* __restrict__ Wg,
                           const float* __restrict__ bg,
                           const float* __restrict__ Wo,
                           const float* __restrict__ bo,
                           float* __restrict__ out) {
    extern __shared__ float sm[];
    float* As = sm;                  // [16][64]   = 4 KB
    float* Bs = sm + 1024;           // [16][256]  = 16 KB
    float* Gs = sm + 1024 + 4096;    // [64][256]  = 64 KB

    int t  = threadIdx.x;
    int tm = t >> 5;   // 0..7  (token group)
    int tn = t & 31;   // 0..31 (column group)
    int n  = blockIdx.y;
    long tok0 = (long)n * SLEN + (long)blockIdx.x * 64;
    const float* ovec = g_o_buf + n * HC;

    float acc[8][8];
    #pragma unroll
    for (int i = 0; i < 8; i++)
        #pragma unroll
        for (int j = 0; j < 8; j++) acc[i][j] = 0.f;

    // ---- GEMM1: M[64,256] @ Wg[256,256] ----
    for (int kk = 0; kk < CIN; kk += 16) {
        {   // A tile: 256 float4s, 1 per thread, store transposed
            int row = t >> 2;
            int cq  = (t & 3) << 2;
            float4 v4 = *reinterpret_cast<const float4*>(
                m + (tok0 + row) * (long)CIN + kk + cq);
            As[(cq + 0) * 64 + row] = v4.x;
            As[(cq + 1) * 64 + row] = v4.y;
            As[(cq + 2) * 64 + row] = v4.z;
            As[(cq + 3) * 64 + row] = v4.w;
        }
        #pragma unroll
        for (int q = 0; q < 4; q++) {  // B tile: 1024 float4s, 4 per thread
            int f  = t + q * 256;
            int k  = f >> 6;
            int j4 = (f & 63) << 2;
            *reinterpret_cast<float4*>(&Bs[k * 256 + j4]) =
                *reinterpret_cast<const float4*>(Wg + (long)(kk + k) * HC + j4);
        }
        __syncthreads();
        #pragma unroll
        for (int k = 0; k < 16; k++) {
            float a[8], b[8];
            *reinterpret_cast<float4*>(a)     = *reinterpret_cast<const float4*>(&As[k * 64 + tm * 8]);
            *reinterpret_cast<float4*>(a + 4) = *reinterpret_cast<const float4*>(&As[k * 64 + tm * 8 + 4]);
            *reinterpret_cast<float4*>(b)     = *reinterpret_cast<const float4*>(&Bs[k * 256 + tn * 8]);
            *reinterpret_cast<float4*>(b + 4) = *reinterpret_cast<const float4*>(&Bs[k * 256 + tn * 8 + 4]);
            #pragma unroll
            for (int i = 0; i < 8; i++)
                #pragma unroll
                for (int j = 0; j < 8; j++)
                    acc[i][j] = fmaf(a[i], b[j], acc[i][j]);
        }
        __syncthreads();
    }

    // ---- epilogue 1: sigmoid gate * o, stage G to smem ----
    #pragma unroll
    for (int j = 0; j < 8; j++) {
        int col   = tn * 8 + j;
        float bgv = bg[col];
        float og  = ovec[col];
        #pragma unroll
        for (int i = 0; i < 8; i++) {
            float x = acc[i][j] + bgv;
            acc[i][j] = og / (1.f + __expf(-x));
        }
    }
    #pragma unroll
    for (int i = 0; i < 8; i++) {
        int row = tm * 8 + i;
        #pragma unroll
        for (int j = 0; j < 8; j += 4) {
            float4 v4 = make_float4(acc[i][j], acc[i][j + 1], acc[i][j + 2], acc[i][j + 3]);
            *reinterpret_cast<float4*>(&Gs[row * 256 + tn * 8 + j]) = v4;
        }
    }
    __syncthreads();

    // ---- GEMM2: G[64,256] @ Wo[256,256] ----
    #pragma unroll
    for (int i = 0; i < 8; i++)
        #pragma unroll
        for (int j = 0; j < 8; j++) acc[i][j] = 0.f;

    for (int kk = 0; kk < HC; kk += 16) {
        #pragma unroll
        for (int q = 0; q < 4; q++) {
            int f  = t + q * 256;
            int k  = f >> 6;
            int j4 = (f & 63) << 2;
            *reinterpret_cast<float4*>(&Bs[k * 256 + j4]) =
                *reinterpret_cast<const float4*>(Wo + (long)(kk + k) * CIN + j4);
        }
        __syncthreads();
        #pragma unroll
        for (int k = 0; k < 16; k++) {
            float a[8], b[8];
            #pragma unroll
            for (int i = 0; i < 8; i++)
                a[i] = Gs[(tm * 8 + i) * 256 + kk + k];  // warp-broadcast reads
            *reinterpret_cast<float4*>(b)     = *reinterpret_cast<const float4*>(&Bs[k * 256 + tn * 8]);
            *reinterpret_cast<float4*>(b + 4) = *reinterpret_cast<const float4*>(&Bs[k * 256 + tn * 8 + 4]);
            #pragma unroll
            for (int i = 0; i < 8; i++)
                #pragma unroll
                for (int j = 0; j < 8; j++)
                    acc[i][j] = fmaf(a[i], b[j], acc[i][j]);
        }
        __syncthreads();
    }

    // ---- epilogue 2: + bo, write out ----
    #pragma unroll
    for (int i = 0; i < 8; i++) {
        long row = tok0 + tm * 8 + i;
        #pragma unroll
        for (int j = 0; j < 8; j += 4) {
            int col = tn * 8 + j;
            float4 v4 = make_float4(acc[i][j]     + bo[col],
                                    acc[i][j + 1] + bo[col + 1],
                                    acc[i][j + 2] + bo[col + 2],
                                    acc[i][j + 3] + bo[col + 3]);
            *reinterpret_cast<float4*>(out + row * (long)CIN + col) = v4;
        }
    }
}

// ---------------------------------------------------------------------------
extern "C" void kernel_launch(void* const* d_in, const int* in_sizes, int n_in,
                              void* d_out, int out_size) {
    const float* m    = (const float*)d_in[0];
    const float* mask = (const float*)d_in[1];
    const float* Wq   = (const float*)d_in[2];
    const float* Wk   = (const float*)d_in[3];
    const float* Wv   = (const float*)d_in[4];
    const float* Wg   = (const float*)d_in[5];
    const float* bg   = (const float*)d_in[6];
    const float* Wo   = (const float*)d_in[7];
    const float* bo   = (const float*)d_in[8];
    float* out = (float*)d_out;

    q_kernel<<<NROWS, 256>>>(m, mask, Wq);
    kv_kernel<<<(NROWS * SLEN) / 128, 128>>>(m, Wk, Wv);
    attn_kernel<<<NROWS, 256>>>(mask);

    cudaFuncSetAttribute(out_kernel,
                         cudaFuncAttributeMaxDynamicSharedMemorySize, 86016);
    out_kernel<<<dim3(SLEN / 64, NROWS), 256, 86016>>>(m, Wg, bg, Wo, bo, out);
}

// round 4
// speedup vs baseline: 1.3165x; 1.3165x over previous
#include <cuda_runtime.h>
#include <math.h>

#define NROWS 384
#define SLEN  1024
#define CIN   256
#define CH    32
#define NH    8
#define HC    256   // NH*CH

// Scratch (no cudaMalloc allowed): ~101 MB of __device__ globals.
__device__ float g_q_buf[NROWS * HC];
__device__ float g_o_buf[NROWS * HC];
__device__ float g_k_buf[(size_t)NROWS * SLEN * CH];
__device__ float g_v_buf[(size_t)NROWS * SLEN * CH];

// ---------------------------------------------------------------------------
// Kernel 1: masked mean over S, then q = (mean @ Wq) * C^-0.5
// grid = 384 rows, block = 256 (thread t = channel / output column)
// ---------------------------------------------------------------------------
__global__ void q_kernel(const float* __restrict__ m,
                         const float* __restrict__ mask,
                         const float* __restrict__ Wq) {
    int n = blockIdx.x, t = threadIdx.x;
    const float* mrow = m + (size_t)n * SLEN * CIN;
    const float* mk   = mask + (size_t)n * SLEN;

    float qs = 0.f;
    #pragma unroll 4
    for (int s = 0; s < SLEN; s++) {
        qs = fmaf(mrow[(size_t)s * CIN + t], mk[s], qs);
    }
    float ms = 0.f;
    for (int s = t; s < SLEN; s += 256) ms += mk[s];

    __shared__ float red[256];
    red[t] = ms;
    __syncthreads();
    for (int off = 128; off > 0; off >>= 1) {
        if (t < off) red[t] += red[t + off];
        __syncthreads();
    }
    float denom = red[0] + 1e-10f;

    __shared__ float qm[CIN];
    qm[t] = qs / denom;
    __syncthreads();

    float acc = 0.f;
    #pragma unroll 8
    for (int c = 0; c < CIN; c++) acc = fmaf(qm[c], Wq[c * HC + t], acc);
    g_q_buf[n * HC + t] = acc * 0.17677669529663687f;  // 32^-0.5
}

// ---------------------------------------------------------------------------
// Kernel 2: k = m@Wk, v = m@Wv as one [393216,256]@[256,64] SGEMM
// BM=128, BN=64, BK=16, 128 threads, 8x8 register tile per thread
// ---------------------------------------------------------------------------
__global__ void kv_kernel(const float* __restrict__ m,
                          const float* __restrict__ Wk,
                          const float* __restrict__ Wv) {
    __shared__ float As[16][128];
    __shared__ float Bs[16][64];
    int t  = threadIdx.x;
    int tm = t >> 3;   // 0..15
    int tn = t & 7;    // 0..7
    long r0 = (long)blockIdx.x * 128;

    float acc[8][8];
    #pragma unroll
    for (int i = 0; i < 8; i++)
        #pragma unroll
        for (int j = 0; j < 8; j++) acc[i][j] = 0.f;

    for (int kk = 0; kk < CIN; kk += 16) {
        // load A tile (transposed into smem): 512 float4s, 4 per thread
        #pragma unroll
        for (int q = 0; q < 4; q++) {
            int f   = t + q * 128;
            int row = f >> 2;
            int cq  = (f & 3) << 2;
            float4 v4 = *reinterpret_cast<const float4*>(
                m + (r0 + row) * (long)CIN + kk + cq);
            As[cq + 0][row] = v4.x;
            As[cq + 1][row] = v4.y;
            As[cq + 2][row] = v4.z;
            As[cq + 3][row] = v4.w;
        }
        // load B tile (Wk || Wv): 256 float4s, 2 per thread
        #pragma unroll
        for (int q = 0; q < 2; q++) {
            int f  = t + q * 128;
            int k  = f >> 4;
            int j4 = f & 15;
            float4 v4;
            if (j4 < 8)
                v4 = *reinterpret_cast<const float4*>(Wk + (kk + k) * CH + j4 * 4);
            else
                v4 = *reinterpret_cast<const float4*>(Wv + (kk + k) * CH + (j4 - 8) * 4);
            *reinterpret_cast<float4*>(&Bs[k][j4 * 4]) = v4;
        }
        __syncthreads();

        #pragma unroll
        for (int k = 0; k < 16; k++) {
            float a[8], b[8];
            *reinterpret_cast<float4*>(a)     = *reinterpret_cast<const float4*>(&As[k][tm * 8]);
            *reinterpret_cast<float4*>(a + 4) = *reinterpret_cast<const float4*>(&As[k][tm * 8 + 4]);
            *reinterpret_cast<float4*>(b)     = *reinterpret_cast<const float4*>(&Bs[k][tn * 8]);
            *reinterpret_cast<float4*>(b + 4) = *reinterpret_cast<const float4*>(&Bs[k][tn * 8 + 4]);
            #pragma unroll
            for (int i = 0; i < 8; i++)
                #pragma unroll
                for (int j = 0; j < 8; j++)
                    acc[i][j] = fmaf(a[i], b[j], acc[i][j]);
        }
        __syncthreads();
    }

    #pragma unroll
    for (int i = 0; i < 8; i++) {
        long r = r0 + tm * 8 + i;
        #pragma unroll
        for (int j = 0; j < 8; j += 4) {
            int col = tn * 8 + j;
            float4 v4 = make_float4(acc[i][j], acc[i][j + 1], acc[i][j + 2], acc[i][j + 3]);
            if (col < CH)
                *reinterpret_cast<float4*>(g_k_buf + r * CH + col) = v4;
            else
                *reinterpret_cast<float4*>(g_v_buf + r * CH + (col - CH)) = v4;
        }
    }
}

// ---------------------------------------------------------------------------
// Kernel 3: logits a[h,s] = q[h]·k[s] + INF*(mask-1), per-head softmax over S,
// o[h,c] = sum_s p[h,s] v[s,c].  grid = 384, block = 256 (8 warps = 8 heads).
// p@v re-tiled: lane = (sg, c4): 4-way s-parallel, 4 channels via LDG.128.
// ---------------------------------------------------------------------------
__global__ void attn_kernel(const float* __restrict__ mask) {
    int n = blockIdx.x, t = threadIdx.x;
    __shared__ float q_sm[HC];
    __shared__ float p_sm[NH * SLEN];  // 32 KB

    q_sm[t] = g_q_buf[n * HC + t];
    __syncthreads();

    const float* krow = g_k_buf + (size_t)n * SLEN * CH;
    const float* vrow = g_v_buf + (size_t)n * SLEN * CH;
    const float* mk   = mask + (size_t)n * SLEN;

    for (int s = t; s < SLEN; s += 256) {
        float kreg[32];
        #pragma unroll
        for (int q = 0; q < 8; q++)
            *reinterpret_cast<float4*>(kreg + q * 4) =
                *reinterpret_cast<const float4*>(krow + (size_t)s * CH + q * 4);
        float bias = 1e9f * (mk[s] - 1.0f);
        #pragma unroll
        for (int h = 0; h < NH; h++) {
            float d = 0.f;
            #pragma unroll
            for (int j = 0; j < 32; j++) d = fmaf(q_sm[h * 32 + j], kreg[j], d);
            p_sm[h * SLEN + s] = d + bias;
        }
    }
    __syncthreads();

    int h = t >> 5, lane = t & 31;
    float mx = -3.0e38f;
    for (int s = lane; s < SLEN; s += 32) mx = fmaxf(mx, p_sm[h * SLEN + s]);
    #pragma unroll
    for (int off = 16; off > 0; off >>= 1)
        mx = fmaxf(mx, __shfl_xor_sync(0xffffffffu, mx, off));

    float sum = 0.f;
    for (int s = lane; s < SLEN; s += 32) {
        float e = __expf(p_sm[h * SLEN + s] - mx);
        p_sm[h * SLEN + s] = e;
        sum += e;
    }
    #pragma unroll
    for (int off = 16; off > 0; off >>= 1)
        sum += __shfl_xor_sync(0xffffffffu, sum, off);
    float inv = 1.f / sum;
    for (int s = lane; s < SLEN; s += 32) p_sm[h * SLEN + s] *= inv;
    __syncthreads();

    // p@v: lane -> (sg = lane>>3 in 0..3, c4 = (lane&7)*4). Each lane
    // accumulates 4 channels over s = sg, sg+4, ... via 128-bit v loads.
    {
        int sg  = lane >> 3;
        int c4  = (lane & 7) << 2;
        float4 acc4 = make_float4(0.f, 0.f, 0.f, 0.f);
        const float* ph = p_sm + h * SLEN;
        #pragma unroll 4
        for (int s = sg; s < SLEN; s += 4) {
            float p = ph[s];
            float4 v4 = *reinterpret_cast<const float4*>(vrow + (size_t)s * CH + c4);
            acc4.x = fmaf(p, v4.x, acc4.x);
            acc4.y = fmaf(p, v4.y, acc4.y);
            acc4.z = fmaf(p, v4.z, acc4.z);
            acc4.w = fmaf(p, v4.w, acc4.w);
        }
        // reduce across the 4 s-groups (lanes differing in bits 3,4)
        #pragma unroll
        for (int off = 8; off <= 16; off <<= 1) {
            acc4.x += __shfl_xor_sync(0xffffffffu, acc4.x, off);
            acc4.y += __shfl_xor_sync(0xffffffffu, acc4.y, off);
            acc4.z += __shfl_xor_sync(0xffffffffu, acc4.z, off);
            acc4.w += __shfl_xor_sync(0xffffffffu, acc4.w, off);
        }
        if (sg == 0)
            *reinterpret_cast<float4*>(g_o_buf + n * HC + h * CH + c4) = acc4;
    }
}

// ---------------------------------------------------------------------------
// Kernel 4 (dominant): per CTA, 64 tokens of one row.
//   G = sigmoid(M@Wg + bg) * o_bcast   (staged fp32 in smem, 64KB)
//   out = G@Wo + bo
// 256 threads, 8x8 register tile, BM=64, BN=256, BK=16.  84 KB dynamic smem.
// __launch_bounds__(256, 2): cap regs at 128 so 2 CTAs/SM fit the regfile
// (was 130 regs -> 1 CTA/SM, occ=12.4%, issue=52%).
// ---------------------------------------------------------------------------
__global__ void __launch_bounds__(256, 2)
out_kernel(const float* __restrict__ m,
           const float* __restrict__ Wg,
           const float* __restrict__ bg,
           const float* __restrict__ Wo,
           const float* __restrict__ bo,
           float* __restrict__ out) {
    extern __shared__ float sm[];
    float* As = sm;                  // [16][64]   = 4 KB
    float* Bs = sm + 1024;           // [16][256]  = 16 KB
    float* Gs = sm + 1024 + 4096;    // [64][256]  = 64 KB

    int t  = threadIdx.x;
    int tm = t >> 5;   // 0..7  (token group)
    int tn = t & 31;   // 0..31 (column group)
    int n  = blockIdx.y;
    long tok0 = (long)n * SLEN + (long)blockIdx.x * 64;
    const float* ovec = g_o_buf + n * HC;

    float acc[8][8];
    #pragma unroll
    for (int i = 0; i < 8; i++)
        #pragma unroll
        for (int j = 0; j < 8; j++) acc[i][j] = 0.f;

    // ---- GEMM1: M[64,256] @ Wg[256,256] ----
    for (int kk = 0; kk < CIN; kk += 16) {
        {   // A tile: 256 float4s, 1 per thread, store transposed
            int row = t >> 2;
            int cq  = (t & 3) << 2;
            float4 v4 = *reinterpret_cast<const float4*>(
                m + (tok0 + row) * (long)CIN + kk + cq);
            As[(cq + 0) * 64 + row] = v4.x;
            As[(cq + 1) * 64 + row] = v4.y;
            As[(cq + 2) * 64 + row] = v4.z;
            As[(cq + 3) * 64 + row] = v4.w;
        }
        #pragma unroll
        for (int q = 0; q < 4; q++) {  // B tile: 1024 float4s, 4 per thread
            int f  = t + q * 256;
            int k  = f >> 6;
            int j4 = (f & 63) << 2;
            *reinterpret_cast<float4*>(&Bs[k * 256 + j4]) =
                *reinterpret_cast<const float4*>(Wg + (long)(kk + k) * HC + j4);
        }
        __syncthreads();
        #pragma unroll
        for (int k = 0; k < 16; k++) {
            float a[8], b[8];
            *reinterpret_cast<float4*>(a)     = *reinterpret_cast<const float4*>(&As[k * 64 + tm * 8]);
            *reinterpret_cast<float4*>(a + 4) = *reinterpret_cast<const float4*>(&As[k * 64 + tm * 8 + 4]);
            *reinterpret_cast<float4*>(b)     = *reinterpret_cast<const float4*>(&Bs[k * 256 + tn * 8]);
            *reinterpret_cast<float4*>(b + 4) = *reinterpret_cast<const float4*>(&Bs[k * 256 + tn * 8 + 4]);
            #pragma unroll
            for (int i = 0; i < 8; i++)
                #pragma unroll
                for (int j = 0; j < 8; j++)
                    acc[i][j] = fmaf(a[i], b[j], acc[i][j]);
        }
        __syncthreads();
    }

    // ---- epilogue 1: sigmoid gate * o, stage G to smem ----
    #pragma unroll
    for (int j = 0; j < 8; j++) {
        int col   = tn * 8 + j;
        float bgv = bg[col];
        float og  = ovec[col];
        #pragma unroll
        for (int i = 0; i < 8; i++) {
            float x = acc[i][j] + bgv;
            acc[i][j] = og / (1.f + __expf(-x));
        }
    }
    #pragma unroll
    for (int i = 0; i < 8; i++) {
        int row = tm * 8 + i;
        #pragma unroll
        for (int j = 0; j < 8; j += 4) {
            float4 v4 = make_float4(acc[i][j], acc[i][j + 1], acc[i][j + 2], acc[i][j + 3]);
            *reinterpret_cast<float4*>(&Gs[row * 256 + tn * 8 + j]) = v4;
        }
    }
    __syncthreads();

    // ---- GEMM2: G[64,256] @ Wo[256,256] ----
    #pragma unroll
    for (int i = 0; i < 8; i++)
        #pragma unroll
        for (int j = 0; j < 8; j++) acc[i][j] = 0.f;

    for (int kk = 0; kk < HC; kk += 16) {
        #pragma unroll
        for (int q = 0; q < 4; q++) {
            int f  = t + q * 256;
            int k  = f >> 6;
            int j4 = (f & 63) << 2;
            *reinterpret_cast<float4*>(&Bs[k * 256 + j4]) =
                *reinterpret_cast<const float4*>(Wo + (long)(kk + k) * CIN + j4);
        }
        __syncthreads();
        #pragma unroll
        for (int k = 0; k < 16; k++) {
            float a[8], b[8];
            #pragma unroll
            for (int i = 0; i < 8; i++)
                a[i] = Gs[(tm * 8 + i) * 256 + kk + k];  // warp-broadcast reads
            *reinterpret_cast<float4*>(b)     = *reinterpret_cast<const float4*>(&Bs[k * 256 + tn * 8]);
            *reinterpret_cast<float4*>(b + 4) = *reinterpret_cast<const float4*>(&Bs[k * 256 + tn * 8 + 4]);
            #pragma unroll
            for (int i = 0; i < 8; i++)
                #pragma unroll
                for (int j = 0; j < 8; j++)
                    acc[i][j] = fmaf(a[i], b[j], acc[i][j]);
        }
        __syncthreads();
    }

    // ---- epilogue 2: + bo, write out ----
    #pragma unroll
    for (int i = 0; i < 8; i++) {
        long row = tok0 + tm * 8 + i;
        #pragma unroll
        for (int j = 0; j < 8; j += 4) {
            int col = tn * 8 + j;
            float4 v4 = make_float4(acc[i][j]     + bo[col],
                                    acc[i][j + 1] + bo[col + 1],
                                    acc[i][j + 2] + bo[col + 2],
                                    acc[i][j + 3] + bo[col + 3]);
            *reinterpret_cast<float4*>(out + row * (long)CIN + col) = v4;
        }
    }
}

// ---------------------------------------------------------------------------
extern "C" void kernel_launch(void* const* d_in, const int* in_sizes, int n_in,
                              void* d_out, int out_size) {
    const float* m    = (const float*)d_in[0];
    const float* mask = (const float*)d_in[1];
    const float* Wq   = (const float*)d_in[2];
    const float* Wk   = (const float*)d_in[3];
    const float* Wv   = (const float*)d_in[4];
    const float* Wg   = (const float*)d_in[5];
    const float* bg   = (const float*)d_in[6];
    const float* Wo   = (const float*)d_in[7];
    const float* bo   = (const float*)d_in[8];
    float* out = (float*)d_out;

    q_kernel<<<NROWS, 256>>>(m, mask, Wq);
    kv_kernel<<<(NROWS * SLEN) / 128, 128>>>(m, Wk, Wv);
    attn_kernel<<<NROWS, 256>>>(mask);

    cudaFuncSetAttribute(out_kernel,
                         cudaFuncAttributeMaxDynamicSharedMemorySize, 86016);
    out_kernel<<<dim3(SLEN / 64, NROWS), 256, 86016>>>(m, Wg, bg, Wo, bo, out);
}

// round 5
// speedup vs baseline: 2.5198x; 1.9140x over previous
#include <cuda_runtime.h>
#include <cuda_bf16.h>
#include <math.h>

#define NROWS 384
#define SLEN  1024
#define CIN   256
#define CH    32
#define NH    8
#define HC    256   // NH*CH

// Scratch (no cudaMalloc allowed).
__device__ float g_q_buf[NROWS * HC];
__device__ float g_o_buf[NROWS * HC];
__device__ float g_k_buf[(size_t)NROWS * SLEN * CH];
__device__ float g_v_buf[(size_t)NROWS * SLEN * CH];
// Pre-split weights (bf16 hi/lo) for tensor-core path.
__device__ __nv_bfloat16 g_WgHi[CIN * HC], g_WgLo[CIN * HC];
__device__ __nv_bfloat16 g_WoHi[HC * CIN], g_WoLo[HC * CIN];

// ---------------------------------------------------------------------------
// Kernel 0: split Wg, Wo into bf16 hi/lo (runs once per launch, ~5us)
// ---------------------------------------------------------------------------
__global__ void wconv_kernel(const float* __restrict__ Wg,
                             const float* __restrict__ Wo) {
    int i = (blockIdx.x * 256 + threadIdx.x) * 4;  // 65536 elems per matrix
    {
        float4 v = *reinterpret_cast<const float4*>(Wg + i);
        __nv_bfloat162 h01 = __floats2bfloat162_rn(v.x, v.y);
        __nv_bfloat162 h23 = __floats2bfloat162_rn(v.z, v.w);
        __nv_bfloat162 l01 = __floats2bfloat162_rn(v.x - __low2float(h01),
                                                   v.y - __high2float(h01));
        __nv_bfloat162 l23 = __floats2bfloat162_rn(v.z - __low2float(h23),
                                                   v.w - __high2float(h23));
        *reinterpret_cast<__nv_bfloat162*>(g_WgHi + i)     = h01;
        *reinterpret_cast<__nv_bfloat162*>(g_WgHi + i + 2) = h23;
        *reinterpret_cast<__nv_bfloat162*>(g_WgLo + i)     = l01;
        *reinterpret_cast<__nv_bfloat162*>(g_WgLo + i + 2) = l23;
    }
    {
        float4 v = *reinterpret_cast<const float4*>(Wo + i);
        __nv_bfloat162 h01 = __floats2bfloat162_rn(v.x, v.y);
        __nv_bfloat162 h23 = __floats2bfloat162_rn(v.z, v.w);
        __nv_bfloat162 l01 = __floats2bfloat162_rn(v.x - __low2float(h01),
                                                   v.y - __high2float(h01));
        __nv_bfloat162 l23 = __floats2bfloat162_rn(v.z - __low2float(h23),
                                                   v.w - __high2float(h23));
        *reinterpret_cast<__nv_bfloat162*>(g_WoHi + i)     = h01;
        *reinterpret_cast<__nv_bfloat162*>(g_WoHi + i + 2) = h23;
        *reinterpret_cast<__nv_bfloat162*>(g_WoLo + i)     = l01;
        *reinterpret_cast<__nv_bfloat162*>(g_WoLo + i + 2) = l23;
    }
}

// ---------------------------------------------------------------------------
// Kernel 1: masked mean over S, then q = (mean @ Wq) * C^-0.5
// ---------------------------------------------------------------------------
__global__ void q_kernel(const float* __restrict__ m,
                         const float* __restrict__ mask,
                         const float* __restrict__ Wq) {
    int n = blockIdx.x, t = threadIdx.x;
    const float* mrow = m + (size_t)n * SLEN * CIN;
    const float* mk   = mask + (size_t)n * SLEN;

    float qs = 0.f;
    #pragma unroll 4
    for (int s = 0; s < SLEN; s++)
        qs = fmaf(mrow[(size_t)s * CIN + t], mk[s], qs);
    float ms = 0.f;
    for (int s = t; s < SLEN; s += 256) ms += mk[s];

    __shared__ float red[256];
    red[t] = ms;
    __syncthreads();
    for (int off = 128; off > 0; off >>= 1) {
        if (t < off) red[t] += red[t + off];
        __syncthreads();
    }
    float denom = red[0] + 1e-10f;

    __shared__ float qm[CIN];
    qm[t] = qs / denom;
    __syncthreads();

    float acc = 0.f;
    #pragma unroll 8
    for (int c = 0; c < CIN; c++) acc = fmaf(qm[c], Wq[c * HC + t], acc);
    g_q_buf[n * HC + t] = acc * 0.17677669529663687f;
}

// ---------------------------------------------------------------------------
// Kernel 2: k = m@Wk, v = m@Wv   (fp32 SIMT, ~secondary cost)
// ---------------------------------------------------------------------------
__global__ void kv_kernel(const float* __restrict__ m,
                          const float* __restrict__ Wk,
                          const float* __restrict__ Wv) {
    __shared__ float As[16][128];
    __shared__ float Bs[16][64];
    int t  = threadIdx.x;
    int tm = t >> 3;
    int tn = t & 7;
    long r0 = (long)blockIdx.x * 128;

    float acc[8][8];
    #pragma unroll
    for (int i = 0; i < 8; i++)
        #pragma unroll
        for (int j = 0; j < 8; j++) acc[i][j] = 0.f;

    for (int kk = 0; kk < CIN; kk += 16) {
        #pragma unroll
        for (int q = 0; q < 4; q++) {
            int f   = t + q * 128;
            int row = f >> 2;
            int cq  = (f & 3) << 2;
            float4 v4 = *reinterpret_cast<const float4*>(
                m + (r0 + row) * (long)CIN + kk + cq);
            As[cq + 0][row] = v4.x;
            As[cq + 1][row] = v4.y;
            As[cq + 2][row] = v4.z;
            As[cq + 3][row] = v4.w;
        }
        #pragma unroll
        for (int q = 0; q < 2; q++) {
            int f  = t + q * 128;
            int k  = f >> 4;
            int j4 = f & 15;
            float4 v4;
            if (j4 < 8)
                v4 = *reinterpret_cast<const float4*>(Wk + (kk + k) * CH + j4 * 4);
            else
                v4 = *reinterpret_cast<const float4*>(Wv + (kk + k) * CH + (j4 - 8) * 4);
            *reinterpret_cast<float4*>(&Bs[k][j4 * 4]) = v4;
        }
        __syncthreads();

        #pragma unroll
        for (int k = 0; k < 16; k++) {
            float a[8], b[8];
            *reinterpret_cast<float4*>(a)     = *reinterpret_cast<const float4*>(&As[k][tm * 8]);
            *reinterpret_cast<float4*>(a + 4) = *reinterpret_cast<const float4*>(&As[k][tm * 8 + 4]);
            *reinterpret_cast<float4*>(b)     = *reinterpret_cast<const float4*>(&Bs[k][tn * 8]);
            *reinterpret_cast<float4*>(b + 4) = *reinterpret_cast<const float4*>(&Bs[k][tn * 8 + 4]);
            #pragma unroll
            for (int i = 0; i < 8; i++)
                #pragma unroll
                for (int j = 0; j < 8; j++)
                    acc[i][j] = fmaf(a[i], b[j], acc[i][j]);
        }
        __syncthreads();
    }

    #pragma unroll
    for (int i = 0; i < 8; i++) {
        long r = r0 + tm * 8 + i;
        #pragma unroll
        for (int j = 0; j < 8; j += 4) {
            int col = tn * 8 + j;
            float4 v4 = make_float4(acc[i][j], acc[i][j + 1], acc[i][j + 2], acc[i][j + 3]);
            if (col < CH)
                *reinterpret_cast<float4*>(g_k_buf + r * CH + col) = v4;
            else
                *reinterpret_cast<float4*>(g_v_buf + r * CH + (col - CH)) = v4;
        }
    }
}

// ---------------------------------------------------------------------------
// Kernel 3: attention (logits + softmax + p@v), fp32
// ---------------------------------------------------------------------------
__global__ void attn_kernel(const float* __restrict__ mask) {
    int n = blockIdx.x, t = threadIdx.x;
    __shared__ float q_sm[HC];
    __shared__ float p_sm[NH * SLEN];

    q_sm[t] = g_q_buf[n * HC + t];
    __syncthreads();

    const float* krow = g_k_buf + (size_t)n * SLEN * CH;
    const float* vrow = g_v_buf + (size_t)n * SLEN * CH;
    const float* mk   = mask + (size_t)n * SLEN;

    for (int s = t; s < SLEN; s += 256) {
        float kreg[32];
        #pragma unroll
        for (int q = 0; q < 8; q++)
            *reinterpret_cast<float4*>(kreg + q * 4) =
                *reinterpret_cast<const float4*>(krow + (size_t)s * CH + q * 4);
        float bias = 1e9f * (mk[s] - 1.0f);
        #pragma unroll
        for (int h = 0; h < NH; h++) {
            float d = 0.f;
            #pragma unroll
            for (int j = 0; j < 32; j++) d = fmaf(q_sm[h * 32 + j], kreg[j], d);
            p_sm[h * SLEN + s] = d + bias;
        }
    }
    __syncthreads();

    int h = t >> 5, lane = t & 31;
    float mx = -3.0e38f;
    for (int s = lane; s < SLEN; s += 32) mx = fmaxf(mx, p_sm[h * SLEN + s]);
    #pragma unroll
    for (int off = 16; off > 0; off >>= 1)
        mx = fmaxf(mx, __shfl_xor_sync(0xffffffffu, mx, off));

    float sum = 0.f;
    for (int s = lane; s < SLEN; s += 32) {
        float e = __expf(p_sm[h * SLEN + s] - mx);
        p_sm[h * SLEN + s] = e;
        sum += e;
    }
    #pragma unroll
    for (int off = 16; off > 0; off >>= 1)
        sum += __shfl_xor_sync(0xffffffffu, sum, off);
    float inv = 1.f / sum;
    for (int s = lane; s < SLEN; s += 32) p_sm[h * SLEN + s] *= inv;
    __syncthreads();

    {
        int sg  = lane >> 3;
        int c4  = (lane & 7) << 2;
        float4 acc4 = make_float4(0.f, 0.f, 0.f, 0.f);
        const float* ph = p_sm + h * SLEN;
        #pragma unroll 4
        for (int s = sg; s < SLEN; s += 4) {
            float p = ph[s];
            float4 v4 = *reinterpret_cast<const float4*>(vrow + (size_t)s * CH + c4);
            acc4.x = fmaf(p, v4.x, acc4.x);
            acc4.y = fmaf(p, v4.y, acc4.y);
            acc4.z = fmaf(p, v4.z, acc4.z);
            acc4.w = fmaf(p, v4.w, acc4.w);
        }
        #pragma unroll
        for (int off = 8; off <= 16; off <<= 1) {
            acc4.x += __shfl_xor_sync(0xffffffffu, acc4.x, off);
            acc4.y += __shfl_xor_sync(0xffffffffu, acc4.y, off);
            acc4.z += __shfl_xor_sync(0xffffffffu, acc4.z, off);
            acc4.w += __shfl_xor_sync(0xffffffffu, acc4.w, off);
        }
        if (sg == 0)
            *reinterpret_cast<float4*>(g_o_buf + n * HC + h * CH + c4) = acc4;
    }
}

// ---------------------------------------------------------------------------
// Kernel 4: tensor-core out_kernel (bf16x3 split, mma.sync.m16n8k16)
// CTA: 64 tokens x 256 cols.  8 warps in 4x2 (16 rows x 128 cols each).
// A (m tile, then G) lives in smem as bf16 hi/lo; Wg/Wo hi/lo chunks streamed.
// ---------------------------------------------------------------------------
#define A_STR   264          // padded row stride (elems) to dodge ldmatrix conflicts
#define AH_OFF  0            // 64 x 264 bf16 = 33792 B
#define AL_OFF  33792
#define BH_OFF  67584        // 16 x 264 bf16 = 8448 B
#define BL_OFF  76032
#define BG_OFF  84480
#define OV_OFF  85504
#define BO_OFF  86528
#define SMEM_BYTES 87552

__device__ __forceinline__ void ldsm4(unsigned r[4], unsigned addr) {
    asm volatile("ldmatrix.sync.aligned.m8n8.x4.shared.b16 {%0,%1,%2,%3}, [%4];"
        : "=r"(r[0]), "=r"(r[1]), "=r"(r[2]), "=r"(r[3]) : "r"(addr));
}
__device__ __forceinline__ void ldsm4t(unsigned r[4], unsigned addr) {
    asm volatile("ldmatrix.sync.aligned.m8n8.x4.trans.shared.b16 {%0,%1,%2,%3}, [%4];"
        : "=r"(r[0]), "=r"(r[1]), "=r"(r[2]), "=r"(r[3]) : "r"(addr));
}
__device__ __forceinline__ void mma_bf16(float c[4], const unsigned a[4],
                                         unsigned b0, unsigned b1) {
    asm volatile("mma.sync.aligned.m16n8k16.row.col.f32.bf16.bf16.f32 "
        "{%0,%1,%2,%3}, {%4,%5,%6,%7}, {%8,%9}, {%0,%1,%2,%3};"
        : "+f"(c[0]), "+f"(c[1]), "+f"(c[2]), "+f"(c[3])
        : "r"(a[0]), "r"(a[1]), "r"(a[2]), "r"(a[3]), "r"(b0), "r"(b1));
}

// One 64x256 GEMM: A (hi/lo in smem) @ W (hi/lo in gmem, streamed), acc += .
__device__ __forceinline__ void gemm_bf16x3(
    char* smc, unsigned sbase,
    const __nv_bfloat16* __restrict__ WHi,
    const __nv_bfloat16* __restrict__ WLo,
    float acc[16][4], int t, int lane, int wm, int wn)
{
    for (int kk = 0; kk < 256; kk += 16) {
        // stream B chunk [16][256] hi+lo into padded smem
        #pragma unroll
        for (int i = 0; i < 2; i++) {
            int f   = t + i * 256;
            int row = f >> 5;
            int c8  = (f & 31) << 3;
            *reinterpret_cast<uint4*>(smc + BH_OFF + (row * A_STR + c8) * 2) =
                *reinterpret_cast<const uint4*>(WHi + (kk + row) * 256 + c8);
            *reinterpret_cast<uint4*>(smc + BL_OFF + (row * A_STR + c8) * 2) =
                *reinterpret_cast<const uint4*>(WLo + (kk + row) * 256 + c8);
        }
        __syncthreads();

        unsigned ah[4], al[4];
        unsigned aaddr = sbase + AH_OFF +
            ((wm * 16 + (lane & 15)) * A_STR + kk + ((lane >> 4) << 3)) * 2;
        ldsm4(ah, aaddr);
        ldsm4(al, aaddr + (AL_OFF - AH_OFF));

        #pragma unroll
        for (int nb = 0; nb < 8; nb++) {
            int n0 = wn * 128 + nb * 16;
            unsigned baddr = sbase + BH_OFF +
                ((lane & 15) * A_STR + n0 + ((lane >> 4) << 3)) * 2;
            unsigned bh[4], bl[4];
            ldsm4t(bh, baddr);
            ldsm4t(bl, baddr + (BL_OFF - BH_OFF));
            // hi*hi + hi*lo + lo*hi  (lo*lo ~2^-18, dropped)
            mma_bf16(acc[nb * 2],     ah, bh[0], bh[1]);
            mma_bf16(acc[nb * 2],     ah, bl[0], bl[1]);
            mma_bf16(acc[nb * 2],     al, bh[0], bh[1]);
            mma_bf16(acc[nb * 2 + 1], ah, bh[2], bh[3]);
            mma_bf16(acc[nb * 2 + 1], ah, bl[2], bl[3]);
            mma_bf16(acc[nb * 2 + 1], al, bh[2], bh[3]);
        }
        __syncthreads();
    }
}

__global__ void __launch_bounds__(256, 2)
out_kernel(const float* __restrict__ m,
           const float* __restrict__ bg,
           const float* __restrict__ bo,
           float* __restrict__ out) {
    extern __shared__ char smc[];
    unsigned sbase = (unsigned)__cvta_generic_to_shared(smc);
    float* sBG = reinterpret_cast<float*>(smc + BG_OFF);
    float* sOV = reinterpret_cast<float*>(smc + OV_OFF);
    float* sBO = reinterpret_cast<float*>(smc + BO_OFF);

    int t = threadIdx.x;
    int lane = t & 31, wid = t >> 5;
    int wm = wid >> 1, wn = wid & 1;
    int n = blockIdx.y;
    long tok0 = (long)n * SLEN + (long)blockIdx.x * 64;

    sBG[t] = bg[t];
    sOV[t] = g_o_buf[n * HC + t];
    sBO[t] = bo[t];

    // load m tile [64][256] fp32 once, split into bf16 hi/lo smem
    #pragma unroll
    for (int i = 0; i < 16; i++) {
        int idx = t + i * 256;
        int row = idx >> 6;
        int c4  = (idx & 63) << 2;
        float4 v = *reinterpret_cast<const float4*>(m + (tok0 + row) * CIN + c4);
        __nv_bfloat162 h01 = __floats2bfloat162_rn(v.x, v.y);
        __nv_bfloat162 h23 = __floats2bfloat162_rn(v.z, v.w);
        __nv_bfloat162 l01 = __floats2bfloat162_rn(v.x - __low2float(h01),
                                                   v.y - __high2float(h01));
        __nv_bfloat162 l23 = __floats2bfloat162_rn(v.z - __low2float(h23),
                                                   v.w - __high2float(h23));
        char* ph = smc + AH_OFF + (row * A_STR + c4) * 2;
        reinterpret_cast<__nv_bfloat162*>(ph)[0] = h01;
        reinterpret_cast<__nv_bfloat162*>(ph)[1] = h23;
        char* pl = smc + AL_OFF + (row * A_STR + c4) * 2;
        reinterpret_cast<__nv_bfloat162*>(pl)[0] = l01;
        reinterpret_cast<__nv_bfloat162*>(pl)[1] = l23;
    }
    __syncthreads();

    float acc[16][4];
    #pragma unroll
    for (int i = 0; i < 16; i++)
        #pragma unroll
        for (int j = 0; j < 4; j++) acc[i][j] = 0.f;

    // ---- GEMM1: M @ Wg ----
    gemm_bf16x3(smc, sbase, g_WgHi, g_WgLo, acc, t, lane, wm, wn);

    // ---- epilogue 1: G = ov * sigmoid(acc + bg), split back into Ah/Al ----
    #pragma unroll
    for (int nt = 0; nt < 16; nt++) {
        int col0 = wn * 128 + nt * 8 + (lane & 3) * 2;
        int r0   = wm * 16 + (lane >> 2);
        float bg0 = sBG[col0], bg1 = sBG[col0 + 1];
        float ov0 = sOV[col0], ov1 = sOV[col0 + 1];
        float g0 = ov0 / (1.f + __expf(-(acc[nt][0] + bg0)));
        float g1 = ov1 / (1.f + __expf(-(acc[nt][1] + bg1)));
        float g2 = ov0 / (1.f + __expf(-(acc[nt][2] + bg0)));
        float g3 = ov1 / (1.f + __expf(-(acc[nt][3] + bg1)));
        __nv_bfloat162 h01 = __floats2bfloat162_rn(g0, g1);
        __nv_bfloat162 l01 = __floats2bfloat162_rn(g0 - __low2float(h01),
                                                   g1 - __high2float(h01));
        __nv_bfloat162 h23 = __floats2bfloat162_rn(g2, g3);
        __nv_bfloat162 l23 = __floats2bfloat162_rn(g2 - __low2float(h23),
                                                   g3 - __high2float(h23));
        *reinterpret_cast<__nv_bfloat162*>(smc + AH_OFF + (r0 * A_STR + col0) * 2)       = h01;
        *reinterpret_cast<__nv_bfloat162*>(smc + AL_OFF + (r0 * A_STR + col0) * 2)       = l01;
        *reinterpret_cast<__nv_bfloat162*>(smc + AH_OFF + ((r0 + 8) * A_STR + col0) * 2) = h23;
        *reinterpret_cast<__nv_bfloat162*>(smc + AL_OFF + ((r0 + 8) * A_STR + col0) * 2) = l23;
        acc[nt][0] = acc[nt][1] = acc[nt][2] = acc[nt][3] = 0.f;
    }
    __syncthreads();

    // ---- GEMM2: G @ Wo ----
    gemm_bf16x3(smc, sbase, g_WoHi, g_WoLo, acc, t, lane, wm, wn);

    // ---- epilogue 2: + bo, write out ----
    #pragma unroll
    for (int nt = 0; nt < 16; nt++) {
        int col0 = wn * 128 + nt * 8 + (lane & 3) * 2;
        int r0   = wm * 16 + (lane >> 2);
        float2 o0 = make_float2(acc[nt][0] + sBO[col0], acc[nt][1] + sBO[col0 + 1]);
        float2 o1 = make_float2(acc[nt][2] + sBO[col0], acc[nt][3] + sBO[col0 + 1]);
        *reinterpret_cast<float2*>(out + (tok0 + r0) * CIN + col0)     = o0;
        *reinterpret_cast<float2*>(out + (tok0 + r0 + 8) * CIN + col0) = o1;
    }
}

// ---------------------------------------------------------------------------
extern "C" void kernel_launch(void* const* d_in, const int* in_sizes, int n_in,
                              void* d_out, int out_size) {
    const float* m    = (const float*)d_in[0];
    const float* mask = (const float*)d_in[1];
    const float* Wq   = (const float*)d_in[2];
    const float* Wk   = (const float*)d_in[3];
    const float* Wv   = (const float*)d_in[4];
    const float* Wg   = (const float*)d_in[5];
    const float* bg   = (const float*)d_in[6];
    const float* Wo   = (const float*)d_in[7];
    const float* bo   = (const float*)d_in[8];
    float* out = (float*)d_out;

    wconv_kernel<<<64, 256>>>(Wg, Wo);
    q_kernel<<<NROWS, 256>>>(m, mask, Wq);
    kv_kernel<<<(NROWS * SLEN) / 128, 128>>>(m, Wk, Wv);
    attn_kernel<<<NROWS, 256>>>(mask);

    cudaFuncSetAttribute(out_kernel,
                         cudaFuncAttributeMaxDynamicSharedMemorySize, SMEM_BYTES);
    out_kernel<<<dim3(SLEN / 64, NROWS), 256, SMEM_BYTES>>>(m, bg, bo, out);
}